// round 8
// baseline (speedup 1.0000x reference)
#include <cuda_runtime.h>
#include <cuda_bf16.h>
#include <math.h>
#include <stdint.h>

// ---------------- Problem constants ----------------
#define BB 2
#define SS 1024
#define DD 768
#define HH 12
#define HD 64
#define LL 4
#define VV 50257
#define BSr (BB*SS)          // 2048
#define D3 (3*DD)            // 2304
#define D4 (4*DD)            // 3072
#define BH (BB*HH)           // 24

// Rounded-weight scratch offsets (floats)
#define OFF_ATTN 0
#define N_ATTN   (LL*DD*D3)
#define OFF_PROJ (OFF_ATTN + N_ATTN)
#define N_PROJ   (LL*DD*DD)
#define OFF_FC   (OFF_PROJ + N_PROJ)
#define N_FC     (LL*DD*D4)
#define OFF_FC2  (OFF_FC + N_FC)
#define N_FC2    (LL*D4*DD)
#define OFF_WTE  (OFF_FC2 + N_FC2)
#define N_WTE    (VV*DD)
#define N_WRND   (OFF_WTE + N_WTE)

// ---------------- Scratch (device globals) ----------------
__device__ float g_h[BSr*DD];
__device__ float g_xln[BSr*DD];
__device__ float g_qkv[BSr*D3];
__device__ float g_abuf[BSr*DD];
__device__ float g_fc[BSr*D4];
__device__ float g_wrnd[N_WRND];

// ---------------- Helpers ----------------
__device__ __forceinline__ float gelu_f(float x) {
    const float c = 0.7978845608028654f;
    float t = tanhf(c * (x + 0.044715f * x * x * x));
    return 0.5f * x * (1.0f + t);
}
__device__ __forceinline__ uint32_t f2tf32(float x) {
    uint32_t r;
    asm("cvt.rna.tf32.f32 %0, %1;" : "=r"(r) : "f"(x));
    return r;
}
__device__ __forceinline__ float tf32rn(float x) { return __uint_as_float(f2tf32(x)); }

__device__ __forceinline__ void mma_tf32(float* c, const uint32_t* a, uint32_t b0, uint32_t b1) {
    asm volatile(
        "mma.sync.aligned.m16n8k8.row.col.f32.tf32.tf32.f32 "
        "{%0,%1,%2,%3}, {%4,%5,%6,%7}, {%8,%9}, {%0,%1,%2,%3};\n"
        : "+f"(c[0]), "+f"(c[1]), "+f"(c[2]), "+f"(c[3])
        : "r"(a[0]), "r"(a[1]), "r"(a[2]), "r"(a[3]), "r"(b0), "r"(b1));
}
__device__ __forceinline__ uint32_t smem_u32(const void* p) {
    return (uint32_t)__cvta_generic_to_shared(p);
}
__device__ __forceinline__ void cpa16(const void* dst, const void* src, int srcbytes) {
    asm volatile("cp.async.ca.shared.global [%0], [%1], 16, %2;\n"
                 :: "r"(smem_u32(dst)), "l"(src), "r"(srcbytes));
}

// ---------------- Preround weights to tf32 ----------------
__global__ void preround_kernel(const float* __restrict__ src, float* __restrict__ dst, int n4) {
    int i = blockIdx.x * blockDim.x + threadIdx.x;
    int stride = gridDim.x * blockDim.x;
    for (; i < n4; i += stride) {
        float4 v = ((const float4*)src)[i];
        v.x = tf32rn(v.x); v.y = tf32rn(v.y); v.z = tf32rn(v.z); v.w = tf32rn(v.w);
        ((float4*)dst)[i] = v;
    }
}

// ---------------- Embedding ----------------
__global__ void embed_kernel(const int* __restrict__ X, const float* __restrict__ wte,
                             const float* __restrict__ wpe, float* __restrict__ h) {
    int bs = blockIdx.x;
    int s = bs & (SS - 1);
    int tok = X[bs];
    const float* we = wte + (size_t)tok * DD;
    const float* wp = wpe + (size_t)s * DD;
    float* out = h + (size_t)bs * DD;
    int tid = threadIdx.x;
#pragma unroll
    for (int q = 0; q < 3; q++) {
        int d = tid + q * 256;
        out[d] = we[d] + wp[d];
    }
}

// ---------------- LayerNorm (rounds output to tf32) ----------------
__global__ void layernorm_kernel(const float* __restrict__ in, const float* __restrict__ g,
                                 const float* __restrict__ b, float* __restrict__ out) {
    int r = blockIdx.x;
    int tid = threadIdx.x;
    const float* x = in + (size_t)r * DD;
    float v0 = x[tid], v1 = x[tid + 256], v2 = x[tid + 512];
    __shared__ float red[256];
    red[tid] = v0 + v1 + v2;
    __syncthreads();
    for (int s = 128; s > 0; s >>= 1) { if (tid < s) red[tid] += red[tid + s]; __syncthreads(); }
    float m = red[0] * (1.0f / DD);
    __syncthreads();
    float d0 = v0 - m, d1 = v1 - m, d2 = v2 - m;
    red[tid] = d0 * d0 + d1 * d1 + d2 * d2;
    __syncthreads();
    for (int s = 128; s > 0; s >>= 1) { if (tid < s) red[tid] += red[tid + s]; __syncthreads(); }
    float inv = rsqrtf(red[0] * (1.0f / DD) + 1e-5f);
    float* o = out + (size_t)r * DD;
    o[tid]       = tf32rn(d0 * inv * g[tid]       + b[tid]);
    o[tid + 256] = tf32rn(d1 * inv * g[tid + 256] + b[tid + 256]);
    o[tid + 512] = tf32rn(d2 * inv * g[tid + 512] + b[tid + 512]);
}

// ---------------- 3-stage pipelined TF32 tensor-core GEMM ----------------
// C[M,N(128 tile)] = A[M,K] @ op(B) + epilogue. Inputs pre-rounded to tf32.
// TM = 128: 8 warps 4(M)x2(N), warp 32x64.  TM = 64: 8 warps 2(M)x4(N), warp 32x32.
// BK=16, 3 smem stages, one __syncthreads per iteration, cp.async FIFO depth 2.
// EPI: 0=bias+rnd, 1=bias+gelu+rnd, 2=bias+residual, 3=plain
// NT: B is [N,K] row-major (logits). GUARD: guard N for B loads + C stores.
template <int EPI, int TM, bool NT, bool GUARD>
__global__ void __launch_bounds__(256, 2)
mma_gemm(const float* __restrict__ A, const float* __restrict__ B,
         const float* __restrict__ bias, const float* __restrict__ res,
         float* __restrict__ C, int M, int N, int K) {
    constexpr int WR = TM / 32;          // warps along M
    constexpr int WC = 8 / WR;           // warps along N
    constexpr int WN = 128 / WC;         // warp N extent
    constexpr int NI = WN / 8;           // n-tiles per warp
    constexpr int ASTR = TM * 20;        // floats per A stage
    constexpr int BSTR = NT ? (128 * 20) : (16 * 132);

    extern __shared__ float sm[];
    float* Asm = sm;
    float* Bsm = sm + 3 * ASTR;

    int tid = threadIdx.x;
    int lane = tid & 31;
    int warp = tid >> 5;
    int gid = lane >> 2, tig = lane & 3;
    int warp_m = warp % WR, warp_n = warp / WR;
    int row_blk = NT ? blockIdx.x : blockIdx.y;
    int col_blk = NT ? blockIdx.y : blockIdx.x;
    int row0 = row_blk * TM, col0 = col_blk * 128;

    float acc[2][NI][4];
#pragma unroll
    for (int mi = 0; mi < 2; mi++)
#pragma unroll
        for (int ni = 0; ni < NI; ni++)
#pragma unroll
            for (int e = 0; e < 4; e++) acc[mi][ni][e] = 0.0f;

    auto stage_fn = [&](int s, int k0) {
        float* As = Asm + s * ASTR;
        float* Bs = Bsm + s * BSTR;
#pragma unroll
        for (int q = 0; q < TM / 64; q++) {
            int cid = tid + q * 256;
            int r = cid >> 2, ch = (cid & 3) * 4;
            cpa16(As + r * 20 + ch, A + (size_t)(row0 + r) * K + k0 + ch, 16);
        }
#pragma unroll
        for (int q = 0; q < 2; q++) {
            int cid = tid + q * 256;
            if (NT) {
                int n = cid >> 2, ch = (cid & 3) * 4;
                bool ok = (!GUARD) || (col0 + n) < N;
                const float* src = ok ? (B + (size_t)(col0 + n) * K + k0 + ch) : B;
                cpa16(Bs + n * 20 + ch, src, ok ? 16 : 0);
            } else {
                int bk = cid >> 5, bn = (cid & 31) * 4;
                cpa16(Bs + bk * 132 + bn, B + (size_t)(k0 + bk) * N + col0 + bn, 16);
            }
        }
        asm volatile("cp.async.commit_group;\n");
    };

    auto compute_fn = [&](int s) {
        const float* As = Asm + s * ASTR;
        const float* Bs = Bsm + s * BSTR;
#pragma unroll
        for (int kk = 0; kk < 2; kk++) {
            int k8 = kk * 8;
            uint32_t af[2][4];
#pragma unroll
            for (int mi = 0; mi < 2; mi++) {
                int rb = warp_m * 32 + mi * 16;
                af[mi][0] = __float_as_uint(As[(rb + gid) * 20 + k8 + tig]);
                af[mi][1] = __float_as_uint(As[(rb + gid + 8) * 20 + k8 + tig]);
                af[mi][2] = __float_as_uint(As[(rb + gid) * 20 + k8 + tig + 4]);
                af[mi][3] = __float_as_uint(As[(rb + gid + 8) * 20 + k8 + tig + 4]);
            }
#pragma unroll
            for (int ni = 0; ni < NI; ni++) {
                int cb = warp_n * WN + ni * 8;
                uint32_t b0, b1;
                if (NT) {
                    b0 = __float_as_uint(Bs[(cb + gid) * 20 + k8 + tig]);
                    b1 = __float_as_uint(Bs[(cb + gid) * 20 + k8 + tig + 4]);
                } else {
                    b0 = __float_as_uint(Bs[(k8 + tig) * 132 + cb + gid]);
                    b1 = __float_as_uint(Bs[(k8 + tig + 4) * 132 + cb + gid]);
                }
                mma_tf32(acc[0][ni], af[0], b0, b1);
                mma_tf32(acc[1][ni], af[1], b0, b1);
            }
        }
    };

    int nIter = K >> 4;                 // K multiple of 16, nIter >= 3 here
    stage_fn(0, 0);
    stage_fn(1, 16);
    for (int i = 0; i < nIter; i++) {
        asm volatile("cp.async.wait_group 1;\n");   // stage i complete (FIFO order)
        __syncthreads();
        if (i + 2 < nIter) stage_fn((i + 2) % 3, (i + 2) << 4);
        else asm volatile("cp.async.commit_group;\n");  // keep FIFO depth invariant
        compute_fn(i % 3);
    }

    // Epilogue
    int row_w = row0 + warp_m * 32;
    int col_w = col0 + warp_n * WN;
#pragma unroll
    for (int mi = 0; mi < 2; mi++) {
        int r0 = row_w + mi * 16 + gid;
        int r1 = r0 + 8;
#pragma unroll
        for (int ni = 0; ni < NI; ni++) {
            int c0 = col_w + ni * 8 + tig * 2;
#pragma unroll
            for (int e = 0; e < 4; e++) {
                int r = (e < 2) ? r0 : r1;
                int c = c0 + (e & 1);
                if (GUARD && c >= N) continue;
                float v = acc[mi][ni][e];
                if (EPI == 0) v = tf32rn(v + bias[c]);
                if (EPI == 1) v = tf32rn(gelu_f(v + bias[c]));
                if (EPI == 2) v = v + bias[c] + res[(size_t)r * N + c];
                C[(size_t)r * N + c] = v;
            }
        }
    }
}

#define SMEM_GEMM(TM, NT) ((3 * ((TM) * 20 + ((NT) ? 2560 : 2112))) * 4)

// ---------------- Fused flash attention (unchanged from R3, proven) ----------------
__global__ void __launch_bounds__(128) flash_kernel(const float* __restrict__ qkv,
                                                    float* __restrict__ out) {
    int it = blockIdx.x, bh = blockIdx.y;
    int b = bh / HH, h = bh % HH;
    int i0 = it * 64;
    int tid = threadIdx.x, lane = tid & 31, warp = tid >> 5;
    int gid = lane >> 2, tig = lane & 3;

    __shared__ float Qs[64][64];
    __shared__ float Ks[64][64];
    __shared__ float Vs[64][64];

#pragma unroll
    for (int q = 0; q < 8; q++) {
        int cid = tid + q * 128;
        int r = cid >> 4, c4 = (cid & 15) * 4;
        float4 v = *(const float4*)(qkv + (size_t)(b * SS + i0 + r) * D3 + h * HD + c4);
        *(float4*)&Qs[r][(c4 + 4 * r) & 63] = v;
    }
    __syncthreads();

    uint32_t qa[8][4];
    int r0 = warp * 16 + gid;
#pragma unroll
    for (int ks = 0; ks < 8; ks++) {
        int k = ks * 8;
        qa[ks][0] = __float_as_uint(Qs[r0][((k + tig) + 4 * r0) & 63]);
        qa[ks][1] = __float_as_uint(Qs[r0 + 8][((k + tig) + 4 * (r0 + 8)) & 63]);
        qa[ks][2] = __float_as_uint(Qs[r0][((k + tig + 4) + 4 * r0) & 63]);
        qa[ks][3] = __float_as_uint(Qs[r0 + 8][((k + tig + 4) + 4 * (r0 + 8)) & 63]);
    }

    float oacc[8][4];
#pragma unroll
    for (int nt = 0; nt < 8; nt++)
#pragma unroll
        for (int e = 0; e < 4; e++) oacc[nt][e] = 0.0f;
    float m_run[2] = {-1e30f, -1e30f};
    float l_run[2] = {0.0f, 0.0f};

    for (int j0 = 0; j0 <= i0; j0 += 64) {
        __syncthreads();
#pragma unroll
        for (int q = 0; q < 8; q++) {
            int cid = tid + q * 128;
            int r = cid >> 4, c4 = (cid & 15) * 4;
            const float* kp = qkv + (size_t)(b * SS + j0 + r) * D3 + DD + h * HD + c4;
            *(float4*)&Ks[r][(c4 + 4 * r) & 63] = *(const float4*)kp;
            *(float4*)&Vs[r][(c4 + 4 * r) & 63] = *(const float4*)(kp + DD);
        }
        __syncthreads();

        float sacc[8][4];
#pragma unroll
        for (int nt = 0; nt < 8; nt++)
#pragma unroll
            for (int e = 0; e < 4; e++) sacc[nt][e] = 0.0f;
#pragma unroll
        for (int ks = 0; ks < 8; ks++) {
            int k8 = ks * 8;
#pragma unroll
            for (int nt = 0; nt < 8; nt++) {
                int n0 = nt * 8 + gid;
                uint32_t b0 = __float_as_uint(Ks[n0][((k8 + tig) + 4 * n0) & 63]);
                uint32_t b1 = __float_as_uint(Ks[n0][((k8 + tig + 4) + 4 * n0) & 63]);
                mma_tf32(sacc[nt], qa[ks], b0, b1);
            }
        }

        bool diag = (j0 == i0);
#pragma unroll
        for (int nt = 0; nt < 8; nt++)
#pragma unroll
            for (int e = 0; e < 4; e++) {
                float s = sacc[nt][e] * 0.125f;
                if (diag) {
                    int rr = warp * 16 + gid + (e >> 1) * 8;
                    int cc = nt * 8 + tig * 2 + (e & 1);
                    if (cc > rr) s = -1e10f;
                }
                sacc[nt][e] = s;
            }

        float mloc[2] = {-1e30f, -1e30f};
#pragma unroll
        for (int nt = 0; nt < 8; nt++)
#pragma unroll
            for (int e = 0; e < 4; e++) mloc[e >> 1] = fmaxf(mloc[e >> 1], sacc[nt][e]);
#pragma unroll
        for (int hh = 0; hh < 2; hh++) {
            mloc[hh] = fmaxf(mloc[hh], __shfl_xor_sync(0xffffffffu, mloc[hh], 1));
            mloc[hh] = fmaxf(mloc[hh], __shfl_xor_sync(0xffffffffu, mloc[hh], 2));
        }
        float mnew[2] = {fmaxf(m_run[0], mloc[0]), fmaxf(m_run[1], mloc[1])};
        float al[2] = {__expf(m_run[0] - mnew[0]), __expf(m_run[1] - mnew[1])};

        float psum[2] = {0.0f, 0.0f};
#pragma unroll
        for (int nt = 0; nt < 8; nt++)
#pragma unroll
            for (int e = 0; e < 4; e++) {
                float p = __expf(sacc[nt][e] - mnew[e >> 1]);
                sacc[nt][e] = p;
                psum[e >> 1] += p;
            }
#pragma unroll
        for (int hh = 0; hh < 2; hh++) {
            psum[hh] += __shfl_xor_sync(0xffffffffu, psum[hh], 1);
            psum[hh] += __shfl_xor_sync(0xffffffffu, psum[hh], 2);
            l_run[hh] = l_run[hh] * al[hh] + psum[hh];
            m_run[hh] = mnew[hh];
        }
#pragma unroll
        for (int nt = 0; nt < 8; nt++)
#pragma unroll
            for (int e = 0; e < 4; e++) oacc[nt][e] *= al[e >> 1];

        int src1 = (gid << 2) + (tig >> 1);
        int src2 = src1 + 2;
#pragma unroll
        for (int ks = 0; ks < 8; ks++) {
            float c0 = sacc[ks][0], c1 = sacc[ks][1], c2 = sacc[ks][2], c3 = sacc[ks][3];
            float v00 = __shfl_sync(0xffffffffu, c0, src1);
            float v01 = __shfl_sync(0xffffffffu, c1, src1);
            float v02 = __shfl_sync(0xffffffffu, c0, src2);
            float v03 = __shfl_sync(0xffffffffu, c1, src2);
            float v10 = __shfl_sync(0xffffffffu, c2, src1);
            float v11 = __shfl_sync(0xffffffffu, c3, src1);
            float v12 = __shfl_sync(0xffffffffu, c2, src2);
            float v13 = __shfl_sync(0xffffffffu, c3, src2);
            uint32_t pa[4];
            bool oddt = (tig & 1);
            pa[0] = f2tf32(oddt ? v01 : v00);
            pa[1] = f2tf32(oddt ? v11 : v10);
            pa[2] = f2tf32(oddt ? v03 : v02);
            pa[3] = f2tf32(oddt ? v13 : v12);
            int k8 = ks * 8;
            int kr0 = k8 + tig, kr1 = k8 + tig + 4;
#pragma unroll
            for (int nt = 0; nt < 8; nt++) {
                int n0 = nt * 8 + gid;
                uint32_t b0 = __float_as_uint(Vs[kr0][(n0 + 4 * kr0) & 63]);
                uint32_t b1 = __float_as_uint(Vs[kr1][(n0 + 4 * kr1) & 63]);
                mma_tf32(oacc[nt], pa, b0, b1);
            }
        }
    }

    float inv[2] = {1.0f / l_run[0], 1.0f / l_run[1]};
#pragma unroll
    for (int nt = 0; nt < 8; nt++)
#pragma unroll
        for (int e = 0; e < 4; e++) {
            int i = i0 + warp * 16 + gid + (e >> 1) * 8;
            int d = nt * 8 + tig * 2 + (e & 1);
            float v = oacc[nt][e] * inv[e >> 1];
            out[(size_t)(b * SS + i) * DD + h * HD + d] = tf32rn(v);
        }
}

// ---------------- Orchestration ----------------
extern "C" void kernel_launch(void* const* d_in, const int* in_sizes, int n_in,
                              void* d_out, int out_size) {
    const int*   X      = (const int*)d_in[0];
    const float* wte    = (const float*)d_in[1];
    const float* wpe    = (const float*)d_in[2];
    const float* ln1_g  = (const float*)d_in[3];
    const float* ln1_b  = (const float*)d_in[4];
    const float* attn_w = (const float*)d_in[5];
    const float* attn_b = (const float*)d_in[6];
    const float* proj_w = (const float*)d_in[7];
    const float* proj_b = (const float*)d_in[8];
    const float* ln2_g  = (const float*)d_in[9];
    const float* ln2_b  = (const float*)d_in[10];
    const float* fc_w   = (const float*)d_in[11];
    const float* fc_b   = (const float*)d_in[12];
    const float* fc2_w  = (const float*)d_in[13];
    const float* fc2_b  = (const float*)d_in[14];
    const float* lnf_g  = (const float*)d_in[15];
    const float* lnf_b  = (const float*)d_in[16];
    float* out = (float*)d_out;

    float *h, *xln, *qkv, *abuf, *fcb, *wr;
    cudaGetSymbolAddress((void**)&h,    g_h);
    cudaGetSymbolAddress((void**)&xln,  g_xln);
    cudaGetSymbolAddress((void**)&qkv,  g_qkv);
    cudaGetSymbolAddress((void**)&abuf, g_abuf);
    cudaGetSymbolAddress((void**)&fcb,  g_fc);
    cudaGetSymbolAddress((void**)&wr,   g_wrnd);

    // Opt-in dynamic smem (>48KB) for the GEMM instantiations
    cudaFuncSetAttribute(mma_gemm<0, 128, false, false>,
                         cudaFuncAttributeMaxDynamicSharedMemorySize, SMEM_GEMM(128, false));
    cudaFuncSetAttribute(mma_gemm<1, 128, false, false>,
                         cudaFuncAttributeMaxDynamicSharedMemorySize, SMEM_GEMM(128, false));
    cudaFuncSetAttribute(mma_gemm<2, 64, false, false>,
                         cudaFuncAttributeMaxDynamicSharedMemorySize, SMEM_GEMM(64, false));
    cudaFuncSetAttribute(mma_gemm<3, 128, true, true>,
                         cudaFuncAttributeMaxDynamicSharedMemorySize, SMEM_GEMM(128, true));

    // Pre-round all weights to tf32 (RN)
    preround_kernel<<<2048, 256>>>(attn_w, wr + OFF_ATTN, N_ATTN / 4);
    preround_kernel<<<2048, 256>>>(proj_w, wr + OFF_PROJ, N_PROJ / 4);
    preround_kernel<<<2048, 256>>>(fc_w,   wr + OFF_FC,   N_FC / 4);
    preround_kernel<<<2048, 256>>>(fc2_w,  wr + OFF_FC2,  N_FC2 / 4);
    preround_kernel<<<4096, 256>>>(wte,    wr + OFF_WTE,  N_WTE / 4);

    embed_kernel<<<BSr, 256>>>(X, wte, wpe, h);

    for (int l = 0; l < LL; l++) {
        layernorm_kernel<<<BSr, 256>>>(h, ln1_g + l * DD, ln1_b + l * DD, xln);
        mma_gemm<0, 128, false, false>
            <<<dim3(D3 / 128, BSr / 128), 256, SMEM_GEMM(128, false)>>>(
            xln, wr + OFF_ATTN + (size_t)l * DD * D3, attn_b + (size_t)l * D3, nullptr,
            qkv, BSr, D3, DD);
        flash_kernel<<<dim3(SS / 64, BH), 128>>>(qkv, abuf);
        mma_gemm<2, 64, false, false>
            <<<dim3(DD / 128, BSr / 64), 256, SMEM_GEMM(64, false)>>>(
            abuf, wr + OFF_PROJ + (size_t)l * DD * DD, proj_b + (size_t)l * DD, h,
            h, BSr, DD, DD);
        layernorm_kernel<<<BSr, 256>>>(h, ln2_g + l * DD, ln2_b + l * DD, xln);
        mma_gemm<1, 128, false, false>
            <<<dim3(D4 / 128, BSr / 128), 256, SMEM_GEMM(128, false)>>>(
            xln, wr + OFF_FC + (size_t)l * DD * D4, fc_b + (size_t)l * D4, nullptr,
            fcb, BSr, D4, DD);
        mma_gemm<2, 64, false, false>
            <<<dim3(DD / 128, BSr / 64), 256, SMEM_GEMM(64, false)>>>(
            fcb, wr + OFF_FC2 + (size_t)l * D4 * DD, fc2_b + (size_t)l * DD, h,
            h, BSr, DD, D4);
    }

    layernorm_kernel<<<BSr, 256>>>(h, lnf_g, lnf_b, xln);
    // Logits: NT, grid x = row tiles (16) so wte col-tiles get L2 reuse across rows
    mma_gemm<3, 128, true, true>
        <<<dim3(BSr / 128, (VV + 127) / 128), 256, SMEM_GEMM(128, true)>>>(
        xln, wr + OFF_WTE, nullptr, nullptr, out, BSr, VV, DD);
}

// round 10
// speedup vs baseline: 1.6386x; 1.6386x over previous
#include <cuda_runtime.h>
#include <cuda_fp16.h>
#include <math.h>
#include <stdint.h>

// ---------------- Problem constants ----------------
#define BB 2
#define SS 1024
#define DD 768
#define HH 12
#define HD 64
#define LL 4
#define VV 50257
#define BSr (BB*SS)          // 2048
#define D3 (3*DD)            // 2304
#define D4 (4*DD)            // 3072
#define BH (BB*HH)           // 24

// Half weight scratch offsets (elements). All stored [N,K] (K-contiguous).
#define OFF_ATTN 0
#define N_ATTN   (LL*DD*D3)
#define OFF_PROJ (OFF_ATTN + N_ATTN)
#define N_PROJ   (LL*DD*DD)
#define OFF_FC   (OFF_PROJ + N_PROJ)
#define N_FC     (LL*DD*D4)
#define OFF_FC2  (OFF_FC + N_FC)
#define N_FC2    (LL*D4*DD)
#define OFF_WTE  (OFF_FC2 + N_FC2)
#define N_WTE    (VV*DD)
#define N_WH     (OFF_WTE + N_WTE)

// ---------------- Scratch (device globals) ----------------
__device__ float  g_h[BSr*DD];
__device__ __half g_xln[BSr*DD];
__device__ float  g_qkv[BSr*D3];
__device__ __half g_abuf[BSr*DD];
__device__ __half g_fc[BSr*D4];
__device__ __half g_wh[N_WH];

// ---------------- Helpers ----------------
__device__ __forceinline__ float gelu_f(float x) {
    const float c = 0.7978845608028654f;
    float t = tanhf(c * (x + 0.044715f * x * x * x));
    return 0.5f * x * (1.0f + t);
}
__device__ __forceinline__ uint32_t f2tf32(float x) {
    uint32_t r;
    asm("cvt.rna.tf32.f32 %0, %1;" : "=r"(r) : "f"(x));
    return r;
}
__device__ __forceinline__ float tf32rn(float x) { return __uint_as_float(f2tf32(x)); }

__device__ __forceinline__ void mma_tf32(float* c, const uint32_t* a, uint32_t b0, uint32_t b1) {
    asm volatile(
        "mma.sync.aligned.m16n8k8.row.col.f32.tf32.tf32.f32 "
        "{%0,%1,%2,%3}, {%4,%5,%6,%7}, {%8,%9}, {%0,%1,%2,%3};\n"
        : "+f"(c[0]), "+f"(c[1]), "+f"(c[2]), "+f"(c[3])
        : "r"(a[0]), "r"(a[1]), "r"(a[2]), "r"(a[3]), "r"(b0), "r"(b1));
}
__device__ __forceinline__ void mma_f16(float* c, const uint32_t* a, uint32_t b0, uint32_t b1) {
    asm volatile(
        "mma.sync.aligned.m16n8k16.row.col.f32.f16.f16.f32 "
        "{%0,%1,%2,%3}, {%4,%5,%6,%7}, {%8,%9}, {%0,%1,%2,%3};\n"
        : "+f"(c[0]), "+f"(c[1]), "+f"(c[2]), "+f"(c[3])
        : "r"(a[0]), "r"(a[1]), "r"(a[2]), "r"(a[3]), "r"(b0), "r"(b1));
}
__device__ __forceinline__ uint32_t smem_u32(const void* p) {
    return (uint32_t)__cvta_generic_to_shared(p);
}
__device__ __forceinline__ void cpa16(const void* dst, const void* src, int srcbytes) {
    asm volatile("cp.async.ca.shared.global [%0], [%1], 16, %2;\n"
                 :: "r"(smem_u32(dst)), "l"(src), "r"(srcbytes));
}

// ---------------- Weight conversion ----------------
// Transpose + convert: dst[N,K] = half(src[K,N]) per layer (z)
__global__ void trph_kernel(const float* __restrict__ src, __half* __restrict__ dst,
                            int K, int N) {
    __shared__ float t[32][33];
    const float* s = src + (size_t)blockIdx.z * K * N;
    __half* d = dst + (size_t)blockIdx.z * N * K;
    int nb = blockIdx.x * 32, kb = blockIdx.y * 32;
    int tx = threadIdx.x, ty = threadIdx.y;
#pragma unroll
    for (int r = 0; r < 4; r++)
        t[ty + 8 * r][tx] = s[(size_t)(kb + ty + 8 * r) * N + nb + tx];
    __syncthreads();
#pragma unroll
    for (int r = 0; r < 4; r++)
        d[(size_t)(nb + ty + 8 * r) * K + kb + tx] = __float2half_rn(t[tx][ty + 8 * r]);
}

// Flat convert float -> half (wte)
__global__ void convh_kernel(const float* __restrict__ src, __half* __restrict__ dst, int n4) {
    int i = blockIdx.x * blockDim.x + threadIdx.x;
    int stride = gridDim.x * blockDim.x;
    for (; i < n4; i += stride) {
        float4 v = ((const float4*)src)[i];
        __half2 h0 = __floats2half2_rn(v.x, v.y);
        __half2 h1 = __floats2half2_rn(v.z, v.w);
        ((uint2*)dst)[i] = make_uint2(*(uint32_t*)&h0, *(uint32_t*)&h1);
    }
}

// ---------------- Embedding ----------------
__global__ void embed_kernel(const int* __restrict__ X, const float* __restrict__ wte,
                             const float* __restrict__ wpe, float* __restrict__ h) {
    int bs = blockIdx.x;
    int s = bs & (SS - 1);
    int tok = X[bs];
    const float* we = wte + (size_t)tok * DD;
    const float* wp = wpe + (size_t)s * DD;
    float* out = h + (size_t)bs * DD;
    int tid = threadIdx.x;
#pragma unroll
    for (int q = 0; q < 3; q++) {
        int d = tid + q * 256;
        out[d] = we[d] + wp[d];
    }
}

// ---------------- LayerNorm (fp32 in, fp16 out for GEMM consumers) ----------------
__global__ void layernorm_kernel(const float* __restrict__ in, const float* __restrict__ g,
                                 const float* __restrict__ b, __half* __restrict__ out) {
    int r = blockIdx.x;
    int tid = threadIdx.x;
    const float* x = in + (size_t)r * DD;
    float v0 = x[tid], v1 = x[tid + 256], v2 = x[tid + 512];
    __shared__ float red[256];
    red[tid] = v0 + v1 + v2;
    __syncthreads();
    for (int s = 128; s > 0; s >>= 1) { if (tid < s) red[tid] += red[tid + s]; __syncthreads(); }
    float m = red[0] * (1.0f / DD);
    __syncthreads();
    float d0 = v0 - m, d1 = v1 - m, d2 = v2 - m;
    red[tid] = d0 * d0 + d1 * d1 + d2 * d2;
    __syncthreads();
    for (int s = 128; s > 0; s >>= 1) { if (tid < s) red[tid] += red[tid + s]; __syncthreads(); }
    float inv = rsqrtf(red[0] * (1.0f / DD) + 1e-5f);
    __half* o = out + (size_t)r * DD;
    o[tid]       = __float2half_rn(d0 * inv * g[tid]       + b[tid]);
    o[tid + 256] = __float2half_rn(d1 * inv * g[tid + 256] + b[tid + 256]);
    o[tid + 512] = __float2half_rn(d2 * inv * g[tid + 512] + b[tid + 512]);
}

// ---------------- FP16 tensor-core GEMM (all NT) ----------------
// C[M,N] = A[M,K] @ Bt[N,K]^T + epilogue. A, Bt are fp16; accumulate fp32.
// TM=128: 8 warps 4(M)x2(N), warp 32x64. TM=64: 2(M)x4(N), warp 32x32.
// BK=32 (two m16n8k16 k-steps per stage), 3 smem stages, 1 sync/iter.
// EPI: 0=bias+tf32rn (float out), 1=bias+gelu (half out), 2=bias+res (float out), 3=plain.
// GUARD: guard N for B loads + C stores (logits).
template <int EPI, int TM, bool GUARD, typename OutT>
__global__ void __launch_bounds__(256, 2)
h_gemm(const __half* __restrict__ A, const __half* __restrict__ Bt,
       const float* __restrict__ bias, const float* __restrict__ res,
       OutT* __restrict__ C, int M, int N, int K) {
    constexpr int WR = TM / 32;
    constexpr int WC = 8 / WR;
    constexpr int WN = 128 / WC;
    constexpr int NI = WN / 8;
    constexpr int ASTR = TM * 40;        // halfs per A stage (pad 8)
    constexpr int BSTR = 128 * 40;

    extern __shared__ __half smh[];
    __half* Asm = smh;
    __half* Bsm = smh + 3 * ASTR;

    int tid = threadIdx.x;
    int lane = tid & 31;
    int warp = tid >> 5;
    int gid = lane >> 2, tig = lane & 3;
    int warp_m = warp % WR, warp_n = warp / WR;
    int row0 = blockIdx.x * TM, col0 = blockIdx.y * 128;

    float acc[2][NI][4];
#pragma unroll
    for (int mi = 0; mi < 2; mi++)
#pragma unroll
        for (int ni = 0; ni < NI; ni++)
#pragma unroll
            for (int e = 0; e < 4; e++) acc[mi][ni][e] = 0.0f;

    auto stage_fn = [&](int s, int k0) {
        __half* As = Asm + s * ASTR;
        __half* Bs = Bsm + s * BSTR;
#pragma unroll
        for (int q = 0; q < TM / 64; q++) {
            int cid = tid + q * 256;
            int r = cid >> 2, ch = (cid & 3) * 8;
            cpa16(As + r * 40 + ch, A + (size_t)(row0 + r) * K + k0 + ch, 16);
        }
#pragma unroll
        for (int q = 0; q < 2; q++) {
            int cid = tid + q * 256;
            int n = cid >> 2, ch = (cid & 3) * 8;
            bool ok = (!GUARD) || (col0 + n) < N;
            const __half* src = ok ? (Bt + (size_t)(col0 + n) * K + k0 + ch) : Bt;
            cpa16(Bs + n * 40 + ch, src, ok ? 16 : 0);
        }
        asm volatile("cp.async.commit_group;\n");
    };

    auto compute_fn = [&](int s) {
        const __half* As = Asm + s * ASTR;
        const __half* Bs = Bsm + s * BSTR;
#pragma unroll
        for (int kk = 0; kk < 2; kk++) {
            int kh = kk * 16;
            uint32_t af[2][4];
#pragma unroll
            for (int mi = 0; mi < 2; mi++) {
                int rb = warp_m * 32 + mi * 16;
                af[mi][0] = *(const uint32_t*)&As[(rb + gid) * 40 + kh + tig * 2];
                af[mi][1] = *(const uint32_t*)&As[(rb + gid + 8) * 40 + kh + tig * 2];
                af[mi][2] = *(const uint32_t*)&As[(rb + gid) * 40 + kh + tig * 2 + 8];
                af[mi][3] = *(const uint32_t*)&As[(rb + gid + 8) * 40 + kh + tig * 2 + 8];
            }
#pragma unroll
            for (int ni = 0; ni < NI; ni++) {
                int cb = warp_n * WN + ni * 8;
                uint32_t b0 = *(const uint32_t*)&Bs[(cb + gid) * 40 + kh + tig * 2];
                uint32_t b1 = *(const uint32_t*)&Bs[(cb + gid) * 40 + kh + tig * 2 + 8];
                mma_f16(acc[0][ni], af[0], b0, b1);
                mma_f16(acc[1][ni], af[1], b0, b1);
            }
        }
    };

    int nIter = K >> 5;                 // K multiple of 32, >= 3 stages deep
    stage_fn(0, 0);
    stage_fn(1, 32);
    for (int i = 0; i < nIter; i++) {
        asm volatile("cp.async.wait_group 1;\n");
        __syncthreads();
        if (i + 2 < nIter) stage_fn((i + 2) % 3, (i + 2) << 5);
        else asm volatile("cp.async.commit_group;\n");
        compute_fn(i % 3);
    }

    // Epilogue
    int row_w = row0 + warp_m * 32;
    int col_w = col0 + warp_n * WN;
#pragma unroll
    for (int mi = 0; mi < 2; mi++) {
        int r0 = row_w + mi * 16 + gid;
        int r1 = r0 + 8;
#pragma unroll
        for (int ni = 0; ni < NI; ni++) {
            int c0 = col_w + ni * 8 + tig * 2;
#pragma unroll
            for (int e = 0; e < 4; e++) {
                int r = (e < 2) ? r0 : r1;
                int c = c0 + (e & 1);
                if (GUARD && c >= N) continue;
                float v = acc[mi][ni][e];
                if (EPI == 0) v = tf32rn(v + bias[c]);
                if (EPI == 1) v = gelu_f(v + bias[c]);
                if (EPI == 2) v = v + bias[c] + res[(size_t)r * N + c];
                if (sizeof(OutT) == 2)
                    ((__half*)C)[(size_t)r * N + c] = __float2half_rn(v);
                else
                    ((float*)C)[(size_t)r * N + c] = v;
            }
        }
    }
}

#define SMEMH(TM) (3 * ((TM) + 128) * 40 * 2)

// ---------------- Fused flash attention (tf32, proven; epilogue -> half) ----------------
__global__ void __launch_bounds__(128) flash_kernel(const float* __restrict__ qkv,
                                                    __half* __restrict__ out) {
    int it = blockIdx.x, bh = blockIdx.y;
    int b = bh / HH, h = bh % HH;
    int i0 = it * 64;
    int tid = threadIdx.x, lane = tid & 31, warp = tid >> 5;
    int gid = lane >> 2, tig = lane & 3;

    __shared__ float Qs[64][64];
    __shared__ float Ks[64][64];
    __shared__ float Vs[64][64];

#pragma unroll
    for (int q = 0; q < 8; q++) {
        int cid = tid + q * 128;
        int r = cid >> 4, c4 = (cid & 15) * 4;
        float4 v = *(const float4*)(qkv + (size_t)(b * SS + i0 + r) * D3 + h * HD + c4);
        *(float4*)&Qs[r][(c4 + 4 * r) & 63] = v;
    }
    __syncthreads();

    uint32_t qa[8][4];
    int r0 = warp * 16 + gid;
#pragma unroll
    for (int ks = 0; ks < 8; ks++) {
        int k = ks * 8;
        qa[ks][0] = __float_as_uint(Qs[r0][((k + tig) + 4 * r0) & 63]);
        qa[ks][1] = __float_as_uint(Qs[r0 + 8][((k + tig) + 4 * (r0 + 8)) & 63]);
        qa[ks][2] = __float_as_uint(Qs[r0][((k + tig + 4) + 4 * r0) & 63]);
        qa[ks][3] = __float_as_uint(Qs[r0 + 8][((k + tig + 4) + 4 * (r0 + 8)) & 63]);
    }

    float oacc[8][4];
#pragma unroll
    for (int nt = 0; nt < 8; nt++)
#pragma unroll
        for (int e = 0; e < 4; e++) oacc[nt][e] = 0.0f;
    float m_run[2] = {-1e30f, -1e30f};
    float l_run[2] = {0.0f, 0.0f};

    for (int j0 = 0; j0 <= i0; j0 += 64) {
        __syncthreads();
#pragma unroll
        for (int q = 0; q < 8; q++) {
            int cid = tid + q * 128;
            int r = cid >> 4, c4 = (cid & 15) * 4;
            const float* kp = qkv + (size_t)(b * SS + j0 + r) * D3 + DD + h * HD + c4;
            *(float4*)&Ks[r][(c4 + 4 * r) & 63] = *(const float4*)kp;
            *(float4*)&Vs[r][(c4 + 4 * r) & 63] = *(const float4*)(kp + DD);
        }
        __syncthreads();

        float sacc[8][4];
#pragma unroll
        for (int nt = 0; nt < 8; nt++)
#pragma unroll
            for (int e = 0; e < 4; e++) sacc[nt][e] = 0.0f;
#pragma unroll
        for (int ks = 0; ks < 8; ks++) {
            int k8 = ks * 8;
#pragma unroll
            for (int nt = 0; nt < 8; nt++) {
                int n0 = nt * 8 + gid;
                uint32_t b0 = __float_as_uint(Ks[n0][((k8 + tig) + 4 * n0) & 63]);
                uint32_t b1 = __float_as_uint(Ks[n0][((k8 + tig + 4) + 4 * n0) & 63]);
                mma_tf32(sacc[nt], qa[ks], b0, b1);
            }
        }

        bool diag = (j0 == i0);
#pragma unroll
        for (int nt = 0; nt < 8; nt++)
#pragma unroll
            for (int e = 0; e < 4; e++) {
                float s = sacc[nt][e] * 0.125f;
                if (diag) {
                    int rr = warp * 16 + gid + (e >> 1) * 8;
                    int cc = nt * 8 + tig * 2 + (e & 1);
                    if (cc > rr) s = -1e10f;
                }
                sacc[nt][e] = s;
            }

        float mloc[2] = {-1e30f, -1e30f};
#pragma unroll
        for (int nt = 0; nt < 8; nt++)
#pragma unroll
            for (int e = 0; e < 4; e++) mloc[e >> 1] = fmaxf(mloc[e >> 1], sacc[nt][e]);
#pragma unroll
        for (int hh = 0; hh < 2; hh++) {
            mloc[hh] = fmaxf(mloc[hh], __shfl_xor_sync(0xffffffffu, mloc[hh], 1));
            mloc[hh] = fmaxf(mloc[hh], __shfl_xor_sync(0xffffffffu, mloc[hh], 2));
        }
        float mnew[2] = {fmaxf(m_run[0], mloc[0]), fmaxf(m_run[1], mloc[1])};
        float al[2] = {__expf(m_run[0] - mnew[0]), __expf(m_run[1] - mnew[1])};

        float psum[2] = {0.0f, 0.0f};
#pragma unroll
        for (int nt = 0; nt < 8; nt++)
#pragma unroll
            for (int e = 0; e < 4; e++) {
                float p = __expf(sacc[nt][e] - mnew[e >> 1]);
                sacc[nt][e] = p;
                psum[e >> 1] += p;
            }
#pragma unroll
        for (int hh = 0; hh < 2; hh++) {
            psum[hh] += __shfl_xor_sync(0xffffffffu, psum[hh], 1);
            psum[hh] += __shfl_xor_sync(0xffffffffu, psum[hh], 2);
            l_run[hh] = l_run[hh] * al[hh] + psum[hh];
            m_run[hh] = mnew[hh];
        }
#pragma unroll
        for (int nt = 0; nt < 8; nt++)
#pragma unroll
            for (int e = 0; e < 4; e++) oacc[nt][e] *= al[e >> 1];

        int src1 = (gid << 2) + (tig >> 1);
        int src2 = src1 + 2;
#pragma unroll
        for (int ks = 0; ks < 8; ks++) {
            float c0 = sacc[ks][0], c1 = sacc[ks][1], c2 = sacc[ks][2], c3 = sacc[ks][3];
            float v00 = __shfl_sync(0xffffffffu, c0, src1);
            float v01 = __shfl_sync(0xffffffffu, c1, src1);
            float v02 = __shfl_sync(0xffffffffu, c0, src2);
            float v03 = __shfl_sync(0xffffffffu, c1, src2);
            float v10 = __shfl_sync(0xffffffffu, c2, src1);
            float v11 = __shfl_sync(0xffffffffu, c3, src1);
            float v12 = __shfl_sync(0xffffffffu, c2, src2);
            float v13 = __shfl_sync(0xffffffffu, c3, src2);
            uint32_t pa[4];
            bool oddt = (tig & 1);
            pa[0] = f2tf32(oddt ? v01 : v00);
            pa[1] = f2tf32(oddt ? v11 : v10);
            pa[2] = f2tf32(oddt ? v03 : v02);
            pa[3] = f2tf32(oddt ? v13 : v12);
            int k8 = ks * 8;
            int kr0 = k8 + tig, kr1 = k8 + tig + 4;
#pragma unroll
            for (int nt = 0; nt < 8; nt++) {
                int n0 = nt * 8 + gid;
                uint32_t b0 = __float_as_uint(Vs[kr0][(n0 + 4 * kr0) & 63]);
                uint32_t b1 = __float_as_uint(Vs[kr1][(n0 + 4 * kr1) & 63]);
                mma_tf32(oacc[nt], pa, b0, b1);
            }
        }
    }

    float inv[2] = {1.0f / l_run[0], 1.0f / l_run[1]};
#pragma unroll
    for (int nt = 0; nt < 8; nt++)
#pragma unroll
        for (int e = 0; e < 4; e++) {
            int i = i0 + warp * 16 + gid + (e >> 1) * 8;
            int d = nt * 8 + tig * 2 + (e & 1);
            float v = oacc[nt][e] * inv[e >> 1];
            out[(size_t)(b * SS + i) * DD + h * HD + d] = __float2half_rn(v);
        }
}

// ---------------- Orchestration ----------------
extern "C" void kernel_launch(void* const* d_in, const int* in_sizes, int n_in,
                              void* d_out, int out_size) {
    const int*   X      = (const int*)d_in[0];
    const float* wte    = (const float*)d_in[1];
    const float* wpe    = (const float*)d_in[2];
    const float* ln1_g  = (const float*)d_in[3];
    const float* ln1_b  = (const float*)d_in[4];
    const float* attn_w = (const float*)d_in[5];
    const float* attn_b = (const float*)d_in[6];
    const float* proj_w = (const float*)d_in[7];
    const float* proj_b = (const float*)d_in[8];
    const float* ln2_g  = (const float*)d_in[9];
    const float* ln2_b  = (const float*)d_in[10];
    const float* fc_w   = (const float*)d_in[11];
    const float* fc_b   = (const float*)d_in[12];
    const float* fc2_w  = (const float*)d_in[13];
    const float* fc2_b  = (const float*)d_in[14];
    const float* lnf_g  = (const float*)d_in[15];
    const float* lnf_b  = (const float*)d_in[16];
    float* out = (float*)d_out;

    float *h, *qkv;
    __half *xln, *abuf, *fcb, *wh;
    cudaGetSymbolAddress((void**)&h,    g_h);
    cudaGetSymbolAddress((void**)&xln,  g_xln);
    cudaGetSymbolAddress((void**)&qkv,  g_qkv);
    cudaGetSymbolAddress((void**)&abuf, g_abuf);
    cudaGetSymbolAddress((void**)&fcb,  g_fc);
    cudaGetSymbolAddress((void**)&wh,   g_wh);

    cudaFuncSetAttribute(h_gemm<0, 128, false, float>,
                         cudaFuncAttributeMaxDynamicSharedMemorySize, SMEMH(128));
    cudaFuncSetAttribute(h_gemm<1, 128, false, __half>,
                         cudaFuncAttributeMaxDynamicSharedMemorySize, SMEMH(128));
    cudaFuncSetAttribute(h_gemm<2, 64, false, float>,
                         cudaFuncAttributeMaxDynamicSharedMemorySize, SMEMH(64));
    cudaFuncSetAttribute(h_gemm<3, 128, true, float>,
                         cudaFuncAttributeMaxDynamicSharedMemorySize, SMEMH(128));

    // Weights -> half, transposed to [N,K] (wte already [N,K]: convert only)
    trph_kernel<<<dim3(D3 / 32, DD / 32, LL), dim3(32, 8)>>>(attn_w, wh + OFF_ATTN, DD, D3);
    trph_kernel<<<dim3(DD / 32, DD / 32, LL), dim3(32, 8)>>>(proj_w, wh + OFF_PROJ, DD, DD);
    trph_kernel<<<dim3(D4 / 32, DD / 32, LL), dim3(32, 8)>>>(fc_w,   wh + OFF_FC,   DD, D4);
    trph_kernel<<<dim3(DD / 32, D4 / 32, LL), dim3(32, 8)>>>(fc2_w,  wh + OFF_FC2,  D4, DD);
    convh_kernel<<<4096, 256>>>(wte, wh + OFF_WTE, N_WTE / 4);

    embed_kernel<<<BSr, 256>>>(X, wte, wpe, h);

    for (int l = 0; l < LL; l++) {
        layernorm_kernel<<<BSr, 256>>>(h, ln1_g + l * DD, ln1_b + l * DD, xln);
        h_gemm<0, 128, false, float>
            <<<dim3(BSr / 128, D3 / 128), 256, SMEMH(128)>>>(
            xln, wh + OFF_ATTN + (size_t)l * DD * D3, attn_b + (size_t)l * D3, nullptr,
            qkv, BSr, D3, DD);
        flash_kernel<<<dim3(SS / 64, BH), 128>>>(qkv, abuf);
        h_gemm<2, 64, false, float>
            <<<dim3(BSr / 64, DD / 128), 256, SMEMH(64)>>>(
            abuf, wh + OFF_PROJ + (size_t)l * DD * DD, proj_b + (size_t)l * DD, h,
            h, BSr, DD, DD);
        layernorm_kernel<<<BSr, 256>>>(h, ln2_g + l * DD, ln2_b + l * DD, xln);
        h_gemm<1, 128, false, __half>
            <<<dim3(BSr / 128, D4 / 128), 256, SMEMH(128)>>>(
            xln, wh + OFF_FC + (size_t)l * DD * D4, fc_b + (size_t)l * D4, nullptr,
            fcb, BSr, D4, DD);
        h_gemm<2, 64, false, float>
            <<<dim3(BSr / 64, DD / 128), 256, SMEMH(64)>>>(
            fcb, wh + OFF_FC2 + (size_t)l * D4 * DD, fc2_b + (size_t)l * DD, h,
            h, BSr, DD, D4);
    }

    layernorm_kernel<<<BSr, 256>>>(h, lnf_g, lnf_b, xln);
    // Logits: grid x = row tiles (16) so wte col-tiles get L2 reuse across row blocks
    h_gemm<3, 128, true, float>
        <<<dim3(BSr / 128, (VV + 127) / 128), 256, SMEMH(128)>>>(
        xln, wh + OFF_WTE, nullptr, nullptr, out, BSr, VV, DD);
}

// round 11
// speedup vs baseline: 1.6905x; 1.0317x over previous
#include <cuda_runtime.h>
#include <cuda_fp16.h>
#include <math.h>
#include <stdint.h>

// ---------------- Problem constants ----------------
#define BB 2
#define SS 1024
#define DD 768
#define HH 12
#define HD 64
#define LL 4
#define VV 50257
#define BSr (BB*SS)          // 2048
#define D3 (3*DD)            // 2304
#define D4 (4*DD)            // 3072
#define BH (BB*HH)           // 24

// Half weight scratch offsets (elements). All stored [N,K] (K-contiguous).
#define OFF_ATTN 0
#define N_ATTN   (LL*DD*D3)
#define OFF_PROJ (OFF_ATTN + N_ATTN)
#define N_PROJ   (LL*DD*DD)
#define OFF_FC   (OFF_PROJ + N_PROJ)
#define N_FC     (LL*DD*D4)
#define OFF_FC2  (OFF_FC + N_FC)
#define N_FC2    (LL*D4*DD)
#define OFF_WTE  (OFF_FC2 + N_FC2)
#define N_WTE    (VV*DD)
#define N_WH     (OFF_WTE + N_WTE)

// ---------------- Scratch (device globals) ----------------
__device__ float  g_h[BSr*DD];
__device__ __half g_xln[BSr*DD];
__device__ __half g_qkv[BSr*D3];
__device__ __half g_abuf[BSr*DD];
__device__ __half g_fc[BSr*D4];
__device__ __half g_wh[N_WH];

// ---------------- Helpers ----------------
__device__ __forceinline__ float gelu_f(float x) {
    const float c = 0.7978845608028654f;
    float t = tanhf(c * (x + 0.044715f * x * x * x));
    return 0.5f * x * (1.0f + t);
}
__device__ __forceinline__ void mma_f16(float* c, const uint32_t* a, uint32_t b0, uint32_t b1) {
    asm volatile(
        "mma.sync.aligned.m16n8k16.row.col.f32.f16.f16.f32 "
        "{%0,%1,%2,%3}, {%4,%5,%6,%7}, {%8,%9}, {%0,%1,%2,%3};\n"
        : "+f"(c[0]), "+f"(c[1]), "+f"(c[2]), "+f"(c[3])
        : "r"(a[0]), "r"(a[1]), "r"(a[2]), "r"(a[3]), "r"(b0), "r"(b1));
}
__device__ __forceinline__ uint32_t smem_u32(const void* p) {
    return (uint32_t)__cvta_generic_to_shared(p);
}
__device__ __forceinline__ void cpa16(const void* dst, const void* src, int srcbytes) {
    asm volatile("cp.async.ca.shared.global [%0], [%1], 16, %2;\n"
                 :: "r"(smem_u32(dst)), "l"(src), "r"(srcbytes));
}
__device__ __forceinline__ uint32_t packh2(float a, float b) {
    __half2 h = __floats2half2_rn(a, b);
    return *(uint32_t*)&h;
}

// ---------------- Weight conversion ----------------
__global__ void trph_kernel(const float* __restrict__ src, __half* __restrict__ dst,
                            int K, int N) {
    __shared__ float t[32][33];
    const float* s = src + (size_t)blockIdx.z * K * N;
    __half* d = dst + (size_t)blockIdx.z * N * K;
    int nb = blockIdx.x * 32, kb = blockIdx.y * 32;
    int tx = threadIdx.x, ty = threadIdx.y;
#pragma unroll
    for (int r = 0; r < 4; r++)
        t[ty + 8 * r][tx] = s[(size_t)(kb + ty + 8 * r) * N + nb + tx];
    __syncthreads();
#pragma unroll
    for (int r = 0; r < 4; r++)
        d[(size_t)(nb + ty + 8 * r) * K + kb + tx] = __float2half_rn(t[tx][ty + 8 * r]);
}

__global__ void convh_kernel(const float* __restrict__ src, __half* __restrict__ dst, int n4) {
    int i = blockIdx.x * blockDim.x + threadIdx.x;
    int stride = gridDim.x * blockDim.x;
    for (; i < n4; i += stride) {
        float4 v = ((const float4*)src)[i];
        ((uint2*)dst)[i] = make_uint2(packh2(v.x, v.y), packh2(v.z, v.w));
    }
}

// ---------------- Embedding ----------------
__global__ void embed_kernel(const int* __restrict__ X, const float* __restrict__ wte,
                             const float* __restrict__ wpe, float* __restrict__ h) {
    int bs = blockIdx.x;
    int s = bs & (SS - 1);
    int tok = X[bs];
    const float* we = wte + (size_t)tok * DD;
    const float* wp = wpe + (size_t)s * DD;
    float* out = h + (size_t)bs * DD;
    int tid = threadIdx.x;
#pragma unroll
    for (int q = 0; q < 3; q++) {
        int d = tid + q * 256;
        out[d] = we[d] + wp[d];
    }
}

// ---------------- LayerNorm: warp per row, 8 rows per block ----------------
__global__ void __launch_bounds__(256) layernorm_kernel(
        const float* __restrict__ in, const float* __restrict__ g,
        const float* __restrict__ b, __half* __restrict__ out) {
    int warp = threadIdx.x >> 5, lane = threadIdx.x & 31;
    int r = blockIdx.x * 8 + warp;
    const float4* x = (const float4*)(in + (size_t)r * DD);
    float4 v[6];
    float s = 0.0f;
#pragma unroll
    for (int i = 0; i < 6; i++) {
        v[i] = x[lane + 32 * i];
        s += v[i].x + v[i].y + v[i].z + v[i].w;
    }
#pragma unroll
    for (int o = 16; o > 0; o >>= 1) s += __shfl_xor_sync(0xffffffffu, s, o);
    float m = s * (1.0f / DD);
    float vs = 0.0f;
#pragma unroll
    for (int i = 0; i < 6; i++) {
        v[i].x -= m; v[i].y -= m; v[i].z -= m; v[i].w -= m;
        vs += v[i].x * v[i].x + v[i].y * v[i].y + v[i].z * v[i].z + v[i].w * v[i].w;
    }
#pragma unroll
    for (int o = 16; o > 0; o >>= 1) vs += __shfl_xor_sync(0xffffffffu, vs, o);
    float inv = rsqrtf(vs * (1.0f / DD) + 1e-5f);
    const float4* g4 = (const float4*)g;
    const float4* b4 = (const float4*)b;
    uint2* o2 = (uint2*)(out + (size_t)r * DD);
#pragma unroll
    for (int i = 0; i < 6; i++) {
        int idx = lane + 32 * i;
        float4 gg = g4[idx], bb = b4[idx];
        float y0 = v[i].x * inv * gg.x + bb.x;
        float y1 = v[i].y * inv * gg.y + bb.y;
        float y2 = v[i].z * inv * gg.z + bb.z;
        float y3 = v[i].w * inv * gg.w + bb.w;
        o2[idx] = make_uint2(packh2(y0, y1), packh2(y2, y3));
    }
}

// ---------------- FP16 tensor-core GEMM (all NT) ----------------
// C[M,N] = A[M,K] @ Bt[N,K]^T + epilogue. fp16 in, fp32 accum.
// TM=128: 8 warps 4(M)x2(N), warp 32x64. TM=64: 2(M)x4(N), warp 32x32.
// BK=32, 3 smem stages, 1 sync/iter.
// EPI: 0=bias, 1=bias+gelu, 2=bias+residual, 3=plain. Output type OutT.
template <int EPI, int TM, bool GUARD, typename OutT>
__global__ void __launch_bounds__(256, 2)
h_gemm(const __half* __restrict__ A, const __half* __restrict__ Bt,
       const float* __restrict__ bias, const float* __restrict__ res,
       OutT* __restrict__ C, int M, int N, int K) {
    constexpr int WR = TM / 32;
    constexpr int WC = 8 / WR;
    constexpr int WN = 128 / WC;
    constexpr int NI = WN / 8;
    constexpr int ASTR = TM * 40;
    constexpr int BSTR = 128 * 40;

    extern __shared__ __half smh[];
    __half* Asm = smh;
    __half* Bsm = smh + 3 * ASTR;

    int tid = threadIdx.x;
    int lane = tid & 31;
    int warp = tid >> 5;
    int gid = lane >> 2, tig = lane & 3;
    int warp_m = warp % WR, warp_n = warp / WR;
    int row0 = blockIdx.x * TM, col0 = blockIdx.y * 128;

    float acc[2][NI][4];
#pragma unroll
    for (int mi = 0; mi < 2; mi++)
#pragma unroll
        for (int ni = 0; ni < NI; ni++)
#pragma unroll
            for (int e = 0; e < 4; e++) acc[mi][ni][e] = 0.0f;

    auto stage_fn = [&](int s, int k0) {
        __half* As = Asm + s * ASTR;
        __half* Bs = Bsm + s * BSTR;
#pragma unroll
        for (int q = 0; q < TM / 64; q++) {
            int cid = tid + q * 256;
            int r = cid >> 2, ch = (cid & 3) * 8;
            cpa16(As + r * 40 + ch, A + (size_t)(row0 + r) * K + k0 + ch, 16);
        }
#pragma unroll
        for (int q = 0; q < 2; q++) {
            int cid = tid + q * 256;
            int n = cid >> 2, ch = (cid & 3) * 8;
            bool ok = (!GUARD) || (col0 + n) < N;
            const __half* src = ok ? (Bt + (size_t)(col0 + n) * K + k0 + ch) : Bt;
            cpa16(Bs + n * 40 + ch, src, ok ? 16 : 0);
        }
        asm volatile("cp.async.commit_group;\n");
    };

    auto compute_fn = [&](int s) {
        const __half* As = Asm + s * ASTR;
        const __half* Bs = Bsm + s * BSTR;
#pragma unroll
        for (int kk = 0; kk < 2; kk++) {
            int kh = kk * 16;
            uint32_t af[2][4];
#pragma unroll
            for (int mi = 0; mi < 2; mi++) {
                int rb = warp_m * 32 + mi * 16;
                af[mi][0] = *(const uint32_t*)&As[(rb + gid) * 40 + kh + tig * 2];
                af[mi][1] = *(const uint32_t*)&As[(rb + gid + 8) * 40 + kh + tig * 2];
                af[mi][2] = *(const uint32_t*)&As[(rb + gid) * 40 + kh + tig * 2 + 8];
                af[mi][3] = *(const uint32_t*)&As[(rb + gid + 8) * 40 + kh + tig * 2 + 8];
            }
#pragma unroll
            for (int ni = 0; ni < NI; ni++) {
                int cb = warp_n * WN + ni * 8;
                uint32_t b0 = *(const uint32_t*)&Bs[(cb + gid) * 40 + kh + tig * 2];
                uint32_t b1 = *(const uint32_t*)&Bs[(cb + gid) * 40 + kh + tig * 2 + 8];
                mma_f16(acc[0][ni], af[0], b0, b1);
                mma_f16(acc[1][ni], af[1], b0, b1);
            }
        }
    };

    int nIter = K >> 5;
    stage_fn(0, 0);
    stage_fn(1, 32);
    for (int i = 0; i < nIter; i++) {
        asm volatile("cp.async.wait_group 1;\n");
        __syncthreads();
        if (i + 2 < nIter) stage_fn((i + 2) % 3, (i + 2) << 5);
        else asm volatile("cp.async.commit_group;\n");
        compute_fn(i % 3);
    }

    int row_w = row0 + warp_m * 32;
    int col_w = col0 + warp_n * WN;
#pragma unroll
    for (int mi = 0; mi < 2; mi++) {
        int r0 = row_w + mi * 16 + gid;
        int r1 = r0 + 8;
#pragma unroll
        for (int ni = 0; ni < NI; ni++) {
            int c0 = col_w + ni * 8 + tig * 2;
#pragma unroll
            for (int e = 0; e < 4; e++) {
                int r = (e < 2) ? r0 : r1;
                int c = c0 + (e & 1);
                if (GUARD && c >= N) continue;
                float v = acc[mi][ni][e];
                if (EPI == 0) v = v + bias[c];
                if (EPI == 1) v = gelu_f(v + bias[c]);
                if (EPI == 2) v = v + bias[c] + res[(size_t)r * N + c];
                if (sizeof(OutT) == 2)
                    ((__half*)C)[(size_t)r * N + c] = __float2half_rn(v);
                else
                    ((float*)C)[(size_t)r * N + c] = v;
            }
        }
    }
}

#define SMEMH(TM) (3 * ((TM) + 128) * 40 * 2)

// ---------------- FP16 fused flash attention ----------------
// Block = 64 query rows x 1 head; 128 threads = 4 warps, 16 rows/warp.
// Q,K stored [row][d] with XOR group swizzle; V stored transposed [d][j].
// S=QK^T and O+=PV via mma.m16n8k16; P's A-fragments come directly from
// S's C-fragments (identical thread mapping) — no shuffles.
__global__ void __launch_bounds__(128) flash_kernel(const __half* __restrict__ qkv,
                                                    __half* __restrict__ out) {
    int it = blockIdx.x, bh = blockIdx.y;
    int b = bh / HH, h = bh % HH;
    int i0 = it * 64;
    int tid = threadIdx.x, lane = tid & 31, warp = tid >> 5;
    int gid = lane >> 2, tig = lane & 3;

    __shared__ __half Qs[64 * 64];
    __shared__ __half Ks[64 * 64];
    __shared__ __half Vs[64 * 64];

    // swizzled half-index for [row r][col c] (64-col row, 8-half groups)
#define SWH(r, c) ((r) * 64 + ((((c) >> 3) ^ ((r) & 7)) * 8) + ((c) & 7))

    // Load Q (4 passes, 16B per thread)
#pragma unroll
    for (int q = 0; q < 4; q++) {
        int cid = tid + q * 128;
        int r = cid >> 3, c8 = (cid & 7) * 8;
        uint4 v = *(const uint4*)(qkv + (size_t)(b * SS + i0 + r) * D3 + h * HD + c8);
        *(uint4*)&Qs[SWH(r, c8)] = v;
    }
    __syncthreads();

    // Q fragments (4 k16-steps x 4 regs), reused across all j-tiles
    uint32_t qa[4][4];
    int r0 = warp * 16 + gid;
#pragma unroll
    for (int ks = 0; ks < 4; ks++) {
        int kh = ks * 16;
        qa[ks][0] = *(const uint32_t*)&Qs[SWH(r0,     kh + 2 * tig)];
        qa[ks][1] = *(const uint32_t*)&Qs[SWH(r0 + 8, kh + 2 * tig)];
        qa[ks][2] = *(const uint32_t*)&Qs[SWH(r0,     kh + 8 + 2 * tig)];
        qa[ks][3] = *(const uint32_t*)&Qs[SWH(r0 + 8, kh + 8 + 2 * tig)];
    }

    float oacc[8][4];
#pragma unroll
    for (int nt = 0; nt < 8; nt++)
#pragma unroll
        for (int e = 0; e < 4; e++) oacc[nt][e] = 0.0f;
    float m_run[2] = {-1e30f, -1e30f};
    float l_run[2] = {0.0f, 0.0f};

    for (int j0 = 0; j0 <= i0; j0 += 64) {
        __syncthreads();
        // K natural [j][d]; V transposed [d][j]
#pragma unroll
        for (int q = 0; q < 4; q++) {
            int cid = tid + q * 128;
            int r = cid >> 3, c8 = (cid & 7) * 8;
            const __half* kp = qkv + (size_t)(b * SS + j0 + r) * D3 + DD + h * HD + c8;
            *(uint4*)&Ks[SWH(r, c8)] = *(const uint4*)kp;
            uint4 vv = *(const uint4*)(kp + DD);
            const __half* vh = (const __half*)&vv;
#pragma unroll
            for (int t = 0; t < 8; t++) Vs[SWH(c8 + t, r)] = vh[t];
        }
        __syncthreads();

        // S = Q K^T (fp32 accum)
        float sacc[8][4];
#pragma unroll
        for (int nt = 0; nt < 8; nt++)
#pragma unroll
            for (int e = 0; e < 4; e++) sacc[nt][e] = 0.0f;
#pragma unroll
        for (int ks = 0; ks < 4; ks++) {
            int kh = ks * 16;
#pragma unroll
            for (int nt = 0; nt < 8; nt++) {
                int n0 = nt * 8 + gid;
                uint32_t b0 = *(const uint32_t*)&Ks[SWH(n0, kh + 2 * tig)];
                uint32_t b1 = *(const uint32_t*)&Ks[SWH(n0, kh + 8 + 2 * tig)];
                mma_f16(sacc[nt], qa[ks], b0, b1);
            }
        }

        // scale + causal mask (diagonal tile only)
        bool diag = (j0 == i0);
#pragma unroll
        for (int nt = 0; nt < 8; nt++)
#pragma unroll
            for (int e = 0; e < 4; e++) {
                float s = sacc[nt][e] * 0.125f;
                if (diag) {
                    int rr = warp * 16 + gid + (e >> 1) * 8;
                    int cc = nt * 8 + tig * 2 + (e & 1);
                    if (cc > rr) s = -1e10f;
                }
                sacc[nt][e] = s;
            }

        // online softmax (row-half 0: rows gid, 1: rows gid+8)
        float mloc[2] = {-1e30f, -1e30f};
#pragma unroll
        for (int nt = 0; nt < 8; nt++)
#pragma unroll
            for (int e = 0; e < 4; e++) mloc[e >> 1] = fmaxf(mloc[e >> 1], sacc[nt][e]);
#pragma unroll
        for (int hh = 0; hh < 2; hh++) {
            mloc[hh] = fmaxf(mloc[hh], __shfl_xor_sync(0xffffffffu, mloc[hh], 1));
            mloc[hh] = fmaxf(mloc[hh], __shfl_xor_sync(0xffffffffu, mloc[hh], 2));
        }
        float mnew[2] = {fmaxf(m_run[0], mloc[0]), fmaxf(m_run[1], mloc[1])};
        float al[2] = {__expf(m_run[0] - mnew[0]), __expf(m_run[1] - mnew[1])};

        float psum[2] = {0.0f, 0.0f};
#pragma unroll
        for (int nt = 0; nt < 8; nt++)
#pragma unroll
            for (int e = 0; e < 4; e++) {
                float p = __expf(sacc[nt][e] - mnew[e >> 1]);
                sacc[nt][e] = p;
                psum[e >> 1] += p;
            }
#pragma unroll
        for (int hh = 0; hh < 2; hh++) {
            psum[hh] += __shfl_xor_sync(0xffffffffu, psum[hh], 1);
            psum[hh] += __shfl_xor_sync(0xffffffffu, psum[hh], 2);
            l_run[hh] = l_run[hh] * al[hh] + psum[hh];
            m_run[hh] = mnew[hh];
        }
#pragma unroll
        for (int nt = 0; nt < 8; nt++)
#pragma unroll
            for (int e = 0; e < 4; e++) oacc[nt][e] *= al[e >> 1];

        // O += P V : P A-fragments = packed S C-fragments (no shuffles)
#pragma unroll
        for (int ks = 0; ks < 4; ks++) {
            uint32_t pa[4];
            pa[0] = packh2(sacc[2 * ks][0],     sacc[2 * ks][1]);
            pa[1] = packh2(sacc[2 * ks][2],     sacc[2 * ks][3]);
            pa[2] = packh2(sacc[2 * ks + 1][0], sacc[2 * ks + 1][1]);
            pa[3] = packh2(sacc[2 * ks + 1][2], sacc[2 * ks + 1][3]);
            int kh = ks * 16;
#pragma unroll
            for (int nt = 0; nt < 8; nt++) {
                int n0 = nt * 8 + gid;      // output head-dim index
                uint32_t b0 = *(const uint32_t*)&Vs[SWH(n0, kh + 2 * tig)];
                uint32_t b1 = *(const uint32_t*)&Vs[SWH(n0, kh + 8 + 2 * tig)];
                mma_f16(oacc[nt], pa, b0, b1);
            }
        }
    }

    float inv[2] = {1.0f / l_run[0], 1.0f / l_run[1]};
#pragma unroll
    for (int nt = 0; nt < 8; nt++)
#pragma unroll
        for (int e = 0; e < 4; e++) {
            int i = i0 + warp * 16 + gid + (e >> 1) * 8;
            int d = nt * 8 + tig * 2 + (e & 1);
            float v = oacc[nt][e] * inv[e >> 1];
            out[(size_t)(b * SS + i) * DD + h * HD + d] = __float2half_rn(v);
        }
#undef SWH
}

// ---------------- Orchestration ----------------
extern "C" void kernel_launch(void* const* d_in, const int* in_sizes, int n_in,
                              void* d_out, int out_size) {
    const int*   X      = (const int*)d_in[0];
    const float* wte    = (const float*)d_in[1];
    const float* wpe    = (const float*)d_in[2];
    const float* ln1_g  = (const float*)d_in[3];
    const float* ln1_b  = (const float*)d_in[4];
    const float* attn_w = (const float*)d_in[5];
    const float* attn_b = (const float*)d_in[6];
    const float* proj_w = (const float*)d_in[7];
    const float* proj_b = (const float*)d_in[8];
    const float* ln2_g  = (const float*)d_in[9];
    const float* ln2_b  = (const float*)d_in[10];
    const float* fc_w   = (const float*)d_in[11];
    const float* fc_b   = (const float*)d_in[12];
    const float* fc2_w  = (const float*)d_in[13];
    const float* fc2_b  = (const float*)d_in[14];
    const float* lnf_g  = (const float*)d_in[15];
    const float* lnf_b  = (const float*)d_in[16];
    float* out = (float*)d_out;

    float* h;
    __half *xln, *qkv, *abuf, *fcb, *wh;
    cudaGetSymbolAddress((void**)&h,    g_h);
    cudaGetSymbolAddress((void**)&xln,  g_xln);
    cudaGetSymbolAddress((void**)&qkv,  g_qkv);
    cudaGetSymbolAddress((void**)&abuf, g_abuf);
    cudaGetSymbolAddress((void**)&fcb,  g_fc);
    cudaGetSymbolAddress((void**)&wh,   g_wh);

    cudaFuncSetAttribute(h_gemm<0, 128, false, __half>,
                         cudaFuncAttributeMaxDynamicSharedMemorySize, SMEMH(128));
    cudaFuncSetAttribute(h_gemm<1, 128, false, __half>,
                         cudaFuncAttributeMaxDynamicSharedMemorySize, SMEMH(128));
    cudaFuncSetAttribute(h_gemm<2, 64, false, float>,
                         cudaFuncAttributeMaxDynamicSharedMemorySize, SMEMH(64));
    cudaFuncSetAttribute(h_gemm<3, 128, true, float>,
                         cudaFuncAttributeMaxDynamicSharedMemorySize, SMEMH(128));

    // Weights -> half, transposed to [N,K] (wte already [N,K]: convert only)
    trph_kernel<<<dim3(D3 / 32, DD / 32, LL), dim3(32, 8)>>>(attn_w, wh + OFF_ATTN, DD, D3);
    trph_kernel<<<dim3(DD / 32, DD / 32, LL), dim3(32, 8)>>>(proj_w, wh + OFF_PROJ, DD, DD);
    trph_kernel<<<dim3(D4 / 32, DD / 32, LL), dim3(32, 8)>>>(fc_w,   wh + OFF_FC,   DD, D4);
    trph_kernel<<<dim3(DD / 32, D4 / 32, LL), dim3(32, 8)>>>(fc2_w,  wh + OFF_FC2,  D4, DD);
    convh_kernel<<<4096, 256>>>(wte, wh + OFF_WTE, N_WTE / 4);

    embed_kernel<<<BSr, 256>>>(X, wte, wpe, h);

    for (int l = 0; l < LL; l++) {
        layernorm_kernel<<<BSr / 8, 256>>>(h, ln1_g + l * DD, ln1_b + l * DD, xln);
        h_gemm<0, 128, false, __half>
            <<<dim3(BSr / 128, D3 / 128), 256, SMEMH(128)>>>(
            xln, wh + OFF_ATTN + (size_t)l * DD * D3, attn_b + (size_t)l * D3, nullptr,
            qkv, BSr, D3, DD);
        flash_kernel<<<dim3(SS / 64, BH), 128>>>(qkv, abuf);
        h_gemm<2, 64, false, float>
            <<<dim3(BSr / 64, DD / 128), 256, SMEMH(64)>>>(
            abuf, wh + OFF_PROJ + (size_t)l * DD * DD, proj_b + (size_t)l * DD, h,
            h, BSr, DD, DD);
        layernorm_kernel<<<BSr / 8, 256>>>(h, ln2_g + l * DD, ln2_b + l * DD, xln);
        h_gemm<1, 128, false, __half>
            <<<dim3(BSr / 128, D4 / 128), 256, SMEMH(128)>>>(
            xln, wh + OFF_FC + (size_t)l * DD * D4, fc_b + (size_t)l * D4, nullptr,
            fcb, BSr, D4, DD);
        h_gemm<2, 64, false, float>
            <<<dim3(BSr / 64, DD / 128), 256, SMEMH(64)>>>(
            fcb, wh + OFF_FC2 + (size_t)l * D4 * DD, fc2_b + (size_t)l * DD, h,
            h, BSr, DD, D4);
    }

    layernorm_kernel<<<BSr / 8, 256>>>(h, lnf_g, lnf_b, xln);
    h_gemm<3, 128, true, float>
        <<<dim3(BSr / 128, (VV + 127) / 128), 256, SMEMH(128)>>>(
        xln, wh + OFF_WTE, nullptr, nullptr, out, BSr, VV, DD);
}

// round 15
// speedup vs baseline: 1.9448x; 1.1504x over previous
#include <cuda_runtime.h>
#include <cuda_fp16.h>
#include <math.h>
#include <stdint.h>

// ---------------- Problem constants ----------------
#define BB 2
#define SS 1024
#define DD 768
#define HH 12
#define HD 64
#define LL 4
#define VV 50257
#define BSr (BB*SS)          // 2048
#define D3 (3*DD)            // 2304
#define D4 (4*DD)            // 3072
#define BH (BB*HH)           // 24

// Half weight scratch offsets (elements). All stored [N,K] (K-contiguous).
#define OFF_ATTN 0
#define N_ATTN   (LL*DD*D3)
#define OFF_PROJ (OFF_ATTN + N_ATTN)
#define N_PROJ   (LL*DD*DD)
#define OFF_FC   (OFF_PROJ + N_PROJ)
#define N_FC     (LL*DD*D4)
#define OFF_FC2  (OFF_FC + N_FC)
#define N_FC2    (LL*D4*DD)
#define OFF_WTE  (OFF_FC2 + N_FC2)
#define N_WTE    (VV*DD)
#define N_WH     (OFF_WTE + N_WTE)

// ---------------- Scratch (device globals) ----------------
__device__ float  g_h[BSr*DD];
__device__ __half g_xln[BSr*DD];
__device__ __half g_qkv[BSr*D3];
__device__ __half g_abuf[BSr*DD];
__device__ __half g_fc[BSr*D4];
__device__ __half g_wh[N_WH];

// ---------------- Helpers ----------------
__device__ __forceinline__ float gelu_f(float x) {
    const float c = 0.7978845608028654f;
    float t = tanhf(c * (x + 0.044715f * x * x * x));
    return 0.5f * x * (1.0f + t);
}
__device__ __forceinline__ void mma_f16(float* c, const uint32_t* a, uint32_t b0, uint32_t b1) {
    asm volatile(
        "mma.sync.aligned.m16n8k16.row.col.f32.f16.f16.f32 "
        "{%0,%1,%2,%3}, {%4,%5,%6,%7}, {%8,%9}, {%0,%1,%2,%3};\n"
        : "+f"(c[0]), "+f"(c[1]), "+f"(c[2]), "+f"(c[3])
        : "r"(a[0]), "r"(a[1]), "r"(a[2]), "r"(a[3]), "r"(b0), "r"(b1));
}
__device__ __forceinline__ uint32_t smem_u32(const void* p) {
    return (uint32_t)__cvta_generic_to_shared(p);
}
__device__ __forceinline__ void cpa16(const void* dst, const void* src, int srcbytes) {
    asm volatile("cp.async.ca.shared.global [%0], [%1], 16, %2;\n"
                 :: "r"(smem_u32(dst)), "l"(src), "r"(srcbytes));
}
__device__ __forceinline__ uint32_t packh2(float a, float b) {
    __half2 h = __floats2half2_rn(a, b);
    return *(uint32_t*)&h;
}
__device__ __forceinline__ void ldsm4(uint32_t* d, uint32_t addr) {
    asm volatile("ldmatrix.sync.aligned.m8n8.x4.shared.b16 {%0,%1,%2,%3}, [%4];"
                 : "=r"(d[0]), "=r"(d[1]), "=r"(d[2]), "=r"(d[3]) : "r"(addr));
}

// ---------------- Weight conversion ----------------
__global__ void trph_kernel(const float* __restrict__ src, __half* __restrict__ dst,
                            int K, int N) {
    __shared__ float t[32][33];
    const float* s = src + (size_t)blockIdx.z * K * N;
    __half* d = dst + (size_t)blockIdx.z * N * K;
    int nb = blockIdx.x * 32, kb = blockIdx.y * 32;
    int tx = threadIdx.x, ty = threadIdx.y;
#pragma unroll
    for (int r = 0; r < 4; r++)
        t[ty + 8 * r][tx] = s[(size_t)(kb + ty + 8 * r) * N + nb + tx];
    __syncthreads();
#pragma unroll
    for (int r = 0; r < 4; r++)
        d[(size_t)(nb + ty + 8 * r) * K + kb + tx] = __float2half_rn(t[tx][ty + 8 * r]);
}

__global__ void convh_kernel(const float* __restrict__ src, __half* __restrict__ dst, int n4) {
    int i = blockIdx.x * blockDim.x + threadIdx.x;
    int stride = gridDim.x * blockDim.x;
    for (; i < n4; i += stride) {
        float4 v = ((const float4*)src)[i];
        ((uint2*)dst)[i] = make_uint2(packh2(v.x, v.y), packh2(v.z, v.w));
    }
}

// ---------------- Embedding ----------------
__global__ void embed_kernel(const int* __restrict__ X, const float* __restrict__ wte,
                             const float* __restrict__ wpe, float* __restrict__ h) {
    int bs = blockIdx.x;
    int s = bs & (SS - 1);
    int tok = X[bs];
    const float* we = wte + (size_t)tok * DD;
    const float* wp = wpe + (size_t)s * DD;
    float* out = h + (size_t)bs * DD;
    int tid = threadIdx.x;
#pragma unroll
    for (int q = 0; q < 3; q++) {
        int d = tid + q * 256;
        out[d] = we[d] + wp[d];
    }
}

// ---------------- LayerNorm: warp per row, 8 rows per block ----------------
__global__ void __launch_bounds__(256) layernorm_kernel(
        const float* __restrict__ in, const float* __restrict__ g,
        const float* __restrict__ b, __half* __restrict__ out) {
    int warp = threadIdx.x >> 5, lane = threadIdx.x & 31;
    int r = blockIdx.x * 8 + warp;
    const float4* x = (const float4*)(in + (size_t)r * DD);
    float4 v[6];
    float s = 0.0f;
#pragma unroll
    for (int i = 0; i < 6; i++) {
        v[i] = x[lane + 32 * i];
        s += v[i].x + v[i].y + v[i].z + v[i].w;
    }
#pragma unroll
    for (int o = 16; o > 0; o >>= 1) s += __shfl_xor_sync(0xffffffffu, s, o);
    float m = s * (1.0f / DD);
    float vs = 0.0f;
#pragma unroll
    for (int i = 0; i < 6; i++) {
        v[i].x -= m; v[i].y -= m; v[i].z -= m; v[i].w -= m;
        vs += v[i].x * v[i].x + v[i].y * v[i].y + v[i].z * v[i].z + v[i].w * v[i].w;
    }
#pragma unroll
    for (int o = 16; o > 0; o >>= 1) vs += __shfl_xor_sync(0xffffffffu, vs, o);
    float inv = rsqrtf(vs * (1.0f / DD) + 1e-5f);
    const float4* g4 = (const float4*)g;
    const float4* b4 = (const float4*)b;
    uint2* o2 = (uint2*)(out + (size_t)r * DD);
#pragma unroll
    for (int i = 0; i < 6; i++) {
        int idx = lane + 32 * i;
        float4 gg = g4[idx], bb = b4[idx];
        float y0 = v[i].x * inv * gg.x + bb.x;
        float y1 = v[i].y * inv * gg.y + bb.y;
        float y2 = v[i].z * inv * gg.z + bb.z;
        float y3 = v[i].w * inv * gg.w + bb.w;
        o2[idx] = make_uint2(packh2(y0, y1), packh2(y2, y3));
    }
}

// ---------------- FP16 tensor-core GEMM (all NT, ldmatrix fragments) ----------------
// C[M,N] = A[M,K] @ Bt[N,K]^T + epilogue. fp16 in, fp32 accum.
// TM=128: 8 warps 4(M)x2(N), warp 32x64. TM=64: 2(M)x4(N), warp 32x32.
// BK=32, 3 smem stages, 1 sync/iter. Fragments via ldmatrix.m8n8.x4.
// EPI: 0=bias, 1=bias+gelu, 2=bias+residual, 3=plain. Output type OutT.
template <int EPI, int TM, bool GUARD, typename OutT>
__global__ void __launch_bounds__(256, 2)
h_gemm(const __half* __restrict__ A, const __half* __restrict__ Bt,
       const float* __restrict__ bias, const float* __restrict__ res,
       OutT* __restrict__ C, int M, int N, int K) {
    constexpr int WR = TM / 32;
    constexpr int WC = 8 / WR;
    constexpr int WN = 128 / WC;
    constexpr int NI = WN / 8;
    constexpr int ASTR = TM * 40;
    constexpr int BSTR = 128 * 40;

    extern __shared__ __half smh[];
    __half* Asm = smh;
    __half* Bsm = smh + 3 * ASTR;

    int tid = threadIdx.x;
    int lane = tid & 31;
    int warp = tid >> 5;
    int gid = lane >> 2, tig = lane & 3;
    int warp_m = warp % WR, warp_n = warp / WR;
    int row0 = blockIdx.x * TM, col0 = blockIdx.y * 128;

    // ldmatrix per-lane address components (halfs)
    int a_r = (lane & 7) + ((lane >> 3) & 1) * 8;   // row within 16-row m-tile
    int a_c = (lane >> 4) * 8;                      // k-half select
    int b_n = (lane & 7) + (lane >> 4) * 8;         // n within 16-n pair
    int b_k = ((lane >> 3) & 1) * 8;                // k-half select
    uint32_t Au = smem_u32(Asm), Bu = smem_u32(Bsm);

    float acc[2][NI][4];
#pragma unroll
    for (int mi = 0; mi < 2; mi++)
#pragma unroll
        for (int ni = 0; ni < NI; ni++)
#pragma unroll
            for (int e = 0; e < 4; e++) acc[mi][ni][e] = 0.0f;

    auto stage_fn = [&](int s, int k0) {
        __half* As = Asm + s * ASTR;
        __half* Bs = Bsm + s * BSTR;
#pragma unroll
        for (int q = 0; q < TM / 64; q++) {
            int cid = tid + q * 256;
            int r = cid >> 2, ch = (cid & 3) * 8;
            cpa16(As + r * 40 + ch, A + (size_t)(row0 + r) * K + k0 + ch, 16);
        }
#pragma unroll
        for (int q = 0; q < 2; q++) {
            int cid = tid + q * 256;
            int n = cid >> 2, ch = (cid & 3) * 8;
            bool ok = (!GUARD) || (col0 + n) < N;
            const __half* src = ok ? (Bt + (size_t)(col0 + n) * K + k0 + ch) : Bt;
            cpa16(Bs + n * 40 + ch, src, ok ? 16 : 0);
        }
        asm volatile("cp.async.commit_group;\n");
    };

    auto compute_fn = [&](int s) {
        uint32_t Abase = Au + s * (ASTR * 2);
        uint32_t Bbase = Bu + s * (BSTR * 2);
#pragma unroll
        for (int kk = 0; kk < 2; kk++) {
            int kh = kk * 16;
            uint32_t af[2][4];
#pragma unroll
            for (int mi = 0; mi < 2; mi++) {
                int rb = warp_m * 32 + mi * 16;
                ldsm4(af[mi], Abase + ((rb + a_r) * 40 + kh + a_c) * 2);
            }
            uint32_t bf[NI][2];
#pragma unroll
            for (int j = 0; j < NI / 2; j++) {
                uint32_t d[4];
                ldsm4(d, Bbase + ((warp_n * WN + j * 16 + b_n) * 40 + kh + b_k) * 2);
                bf[2 * j][0] = d[0]; bf[2 * j][1] = d[1];
                bf[2 * j + 1][0] = d[2]; bf[2 * j + 1][1] = d[3];
            }
#pragma unroll
            for (int ni = 0; ni < NI; ni++) {
                mma_f16(acc[0][ni], af[0], bf[ni][0], bf[ni][1]);
                mma_f16(acc[1][ni], af[1], bf[ni][0], bf[ni][1]);
            }
        }
    };

    int nIter = K >> 5;
    stage_fn(0, 0);
    stage_fn(1, 32);
    for (int i = 0; i < nIter; i++) {
        asm volatile("cp.async.wait_group 1;\n");
        __syncthreads();
        if (i + 2 < nIter) stage_fn((i + 2) % 3, (i + 2) << 5);
        else asm volatile("cp.async.commit_group;\n");
        compute_fn(i % 3);
    }

    int row_w = row0 + warp_m * 32;
    int col_w = col0 + warp_n * WN;
#pragma unroll
    for (int mi = 0; mi < 2; mi++) {
        int r0 = row_w + mi * 16 + gid;
        int r1 = r0 + 8;
#pragma unroll
        for (int ni = 0; ni < NI; ni++) {
            int c0 = col_w + ni * 8 + tig * 2;
#pragma unroll
            for (int e = 0; e < 4; e++) {
                int r = (e < 2) ? r0 : r1;
                int c = c0 + (e & 1);
                if (GUARD && c >= N) continue;
                float v = acc[mi][ni][e];
                if (EPI == 0) v = v + bias[c];
                if (EPI == 1) v = gelu_f(v + bias[c]);
                if (EPI == 2) v = v + bias[c] + res[(size_t)r * N + c];
                if (sizeof(OutT) == 2)
                    ((__half*)C)[(size_t)r * N + c] = __float2half_rn(v);
                else
                    ((float*)C)[(size_t)r * N + c] = v;
            }
        }
    }
}

#define SMEMH(TM) (3 * ((TM) + 128) * 40 * 2)

// ---------------- FP16 fused flash attention (proven R7) ----------------
__global__ void __launch_bounds__(128) flash_kernel(const __half* __restrict__ qkv,
                                                    __half* __restrict__ out) {
    int it = blockIdx.x, bh = blockIdx.y;
    int b = bh / HH, h = bh % HH;
    int i0 = it * 64;
    int tid = threadIdx.x, lane = tid & 31, warp = tid >> 5;
    int gid = lane >> 2, tig = lane & 3;

    __shared__ __half Qs[64 * 64];
    __shared__ __half Ks[64 * 64];
    __shared__ __half Vs[64 * 64];

#define SWH(r, c) ((r) * 64 + ((((c) >> 3) ^ ((r) & 7)) * 8) + ((c) & 7))

#pragma unroll
    for (int q = 0; q < 4; q++) {
        int cid = tid + q * 128;
        int r = cid >> 3, c8 = (cid & 7) * 8;
        uint4 v = *(const uint4*)(qkv + (size_t)(b * SS + i0 + r) * D3 + h * HD + c8);
        *(uint4*)&Qs[SWH(r, c8)] = v;
    }
    __syncthreads();

    uint32_t qa[4][4];
    int r0 = warp * 16 + gid;
#pragma unroll
    for (int ks = 0; ks < 4; ks++) {
        int kh = ks * 16;
        qa[ks][0] = *(const uint32_t*)&Qs[SWH(r0,     kh + 2 * tig)];
        qa[ks][1] = *(const uint32_t*)&Qs[SWH(r0 + 8, kh + 2 * tig)];
        qa[ks][2] = *(const uint32_t*)&Qs[SWH(r0,     kh + 8 + 2 * tig)];
        qa[ks][3] = *(const uint32_t*)&Qs[SWH(r0 + 8, kh + 8 + 2 * tig)];
    }

    float oacc[8][4];
#pragma unroll
    for (int nt = 0; nt < 8; nt++)
#pragma unroll
        for (int e = 0; e < 4; e++) oacc[nt][e] = 0.0f;
    float m_run[2] = {-1e30f, -1e30f};
    float l_run[2] = {0.0f, 0.0f};

    for (int j0 = 0; j0 <= i0; j0 += 64) {
        __syncthreads();
#pragma unroll
        for (int q = 0; q < 4; q++) {
            int cid = tid + q * 128;
            int r = cid >> 3, c8 = (cid & 7) * 8;
            const __half* kp = qkv + (size_t)(b * SS + j0 + r) * D3 + DD + h * HD + c8;
            *(uint4*)&Ks[SWH(r, c8)] = *(const uint4*)kp;
            uint4 vv = *(const uint4*)(kp + DD);
            const __half* vh = (const __half*)&vv;
#pragma unroll
            for (int t = 0; t < 8; t++) Vs[SWH(c8 + t, r)] = vh[t];
        }
        __syncthreads();

        float sacc[8][4];
#pragma unroll
        for (int nt = 0; nt < 8; nt++)
#pragma unroll
            for (int e = 0; e < 4; e++) sacc[nt][e] = 0.0f;
#pragma unroll
        for (int ks = 0; ks < 4; ks++) {
            int kh = ks * 16;
#pragma unroll
            for (int nt = 0; nt < 8; nt++) {
                int n0 = nt * 8 + gid;
                uint32_t b0 = *(const uint32_t*)&Ks[SWH(n0, kh + 2 * tig)];
                uint32_t b1 = *(const uint32_t*)&Ks[SWH(n0, kh + 8 + 2 * tig)];
                mma_f16(sacc[nt], qa[ks], b0, b1);
            }
        }

        bool diag = (j0 == i0);
#pragma unroll
        for (int nt = 0; nt < 8; nt++)
#pragma unroll
            for (int e = 0; e < 4; e++) {
                float s = sacc[nt][e] * 0.125f;
                if (diag) {
                    int rr = warp * 16 + gid + (e >> 1) * 8;
                    int cc = nt * 8 + tig * 2 + (e & 1);
                    if (cc > rr) s = -1e10f;
                }
                sacc[nt][e] = s;
            }

        float mloc[2] = {-1e30f, -1e30f};
#pragma unroll
        for (int nt = 0; nt < 8; nt++)
#pragma unroll
            for (int e = 0; e < 4; e++) mloc[e >> 1] = fmaxf(mloc[e >> 1], sacc[nt][e]);
#pragma unroll
        for (int hh = 0; hh < 2; hh++) {
            mloc[hh] = fmaxf(mloc[hh], __shfl_xor_sync(0xffffffffu, mloc[hh], 1));
            mloc[hh] = fmaxf(mloc[hh], __shfl_xor_sync(0xffffffffu, mloc[hh], 2));
        }
        float mnew[2] = {fmaxf(m_run[0], mloc[0]), fmaxf(m_run[1], mloc[1])};
        float al[2] = {__expf(m_run[0] - mnew[0]), __expf(m_run[1] - mnew[1])};

        float psum[2] = {0.0f, 0.0f};
#pragma unroll
        for (int nt = 0; nt < 8; nt++)
#pragma unroll
            for (int e = 0; e < 4; e++) {
                float p = __expf(sacc[nt][e] - mnew[e >> 1]);
                sacc[nt][e] = p;
                psum[e >> 1] += p;
            }
#pragma unroll
        for (int hh = 0; hh < 2; hh++) {
            psum[hh] += __shfl_xor_sync(0xffffffffu, psum[hh], 1);
            psum[hh] += __shfl_xor_sync(0xffffffffu, psum[hh], 2);
            l_run[hh] = l_run[hh] * al[hh] + psum[hh];
            m_run[hh] = mnew[hh];
        }
#pragma unroll
        for (int nt = 0; nt < 8; nt++)
#pragma unroll
            for (int e = 0; e < 4; e++) oacc[nt][e] *= al[e >> 1];

#pragma unroll
        for (int ks = 0; ks < 4; ks++) {
            uint32_t pa[4];
            pa[0] = packh2(sacc[2 * ks][0],     sacc[2 * ks][1]);
            pa[1] = packh2(sacc[2 * ks][2],     sacc[2 * ks][3]);
            pa[2] = packh2(sacc[2 * ks + 1][0], sacc[2 * ks + 1][1]);
            pa[3] = packh2(sacc[2 * ks + 1][2], sacc[2 * ks + 1][3]);
            int kh = ks * 16;
#pragma unroll
            for (int nt = 0; nt < 8; nt++) {
                int n0 = nt * 8 + gid;
                uint32_t b0 = *(const uint32_t*)&Vs[SWH(n0, kh + 2 * tig)];
                uint32_t b1 = *(const uint32_t*)&Vs[SWH(n0, kh + 8 + 2 * tig)];
                mma_f16(oacc[nt], pa, b0, b1);
            }
        }
    }

    float inv[2] = {1.0f / l_run[0], 1.0f / l_run[1]};
#pragma unroll
    for (int nt = 0; nt < 8; nt++)
#pragma unroll
        for (int e = 0; e < 4; e++) {
            int i = i0 + warp * 16 + gid + (e >> 1) * 8;
            int d = nt * 8 + tig * 2 + (e & 1);
            float v = oacc[nt][e] * inv[e >> 1];
            out[(size_t)(b * SS + i) * DD + h * HD + d] = __float2half_rn(v);
        }
#undef SWH
}

// ---------------- Orchestration ----------------
extern "C" void kernel_launch(void* const* d_in, const int* in_sizes, int n_in,
                              void* d_out, int out_size) {
    const int*   X      = (const int*)d_in[0];
    const float* wte    = (const float*)d_in[1];
    const float* wpe    = (const float*)d_in[2];
    const float* ln1_g  = (const float*)d_in[3];
    const float* ln1_b  = (const float*)d_in[4];
    const float* attn_w = (const float*)d_in[5];
    const float* attn_b = (const float*)d_in[6];
    const float* proj_w = (const float*)d_in[7];
    const float* proj_b = (const float*)d_in[8];
    const float* ln2_g  = (const float*)d_in[9];
    const float* ln2_b  = (const float*)d_in[10];
    const float* fc_w   = (const float*)d_in[11];
    const float* fc_b   = (const float*)d_in[12];
    const float* fc2_w  = (const float*)d_in[13];
    const float* fc2_b  = (const float*)d_in[14];
    const float* lnf_g  = (const float*)d_in[15];
    const float* lnf_b  = (const float*)d_in[16];
    float* out = (float*)d_out;

    float* h;
    __half *xln, *qkv, *abuf, *fcb, *wh;
    cudaGetSymbolAddress((void**)&h,    g_h);
    cudaGetSymbolAddress((void**)&xln,  g_xln);
    cudaGetSymbolAddress((void**)&qkv,  g_qkv);
    cudaGetSymbolAddress((void**)&abuf, g_abuf);
    cudaGetSymbolAddress((void**)&fcb,  g_fc);
    cudaGetSymbolAddress((void**)&wh,   g_wh);

    cudaFuncSetAttribute(h_gemm<0, 128, false, __half>,
                         cudaFuncAttributeMaxDynamicSharedMemorySize, SMEMH(128));
    cudaFuncSetAttribute(h_gemm<1, 128, false, __half>,
                         cudaFuncAttributeMaxDynamicSharedMemorySize, SMEMH(128));
    cudaFuncSetAttribute(h_gemm<2, 64, false, float>,
                         cudaFuncAttributeMaxDynamicSharedMemorySize, SMEMH(64));
    cudaFuncSetAttribute(h_gemm<3, 128, true, float>,
                         cudaFuncAttributeMaxDynamicSharedMemorySize, SMEMH(128));

    trph_kernel<<<dim3(D3 / 32, DD / 32, LL), dim3(32, 8)>>>(attn_w, wh + OFF_ATTN, DD, D3);
    trph_kernel<<<dim3(DD / 32, DD / 32, LL), dim3(32, 8)>>>(proj_w, wh + OFF_PROJ, DD, DD);
    trph_kernel<<<dim3(D4 / 32, DD / 32, LL), dim3(32, 8)>>>(fc_w,   wh + OFF_FC,   DD, D4);
    trph_kernel<<<dim3(DD / 32, D4 / 32, LL), dim3(32, 8)>>>(fc2_w,  wh + OFF_FC2,  D4, DD);
    convh_kernel<<<4096, 256>>>(wte, wh + OFF_WTE, N_WTE / 4);

    embed_kernel<<<BSr, 256>>>(X, wte, wpe, h);

    for (int l = 0; l < LL; l++) {
        layernorm_kernel<<<BSr / 8, 256>>>(h, ln1_g + l * DD, ln1_b + l * DD, xln);
        h_gemm<0, 128, false, __half>
            <<<dim3(BSr / 128, D3 / 128), 256, SMEMH(128)>>>(
            xln, wh + OFF_ATTN + (size_t)l * DD * D3, attn_b + (size_t)l * D3, nullptr,
            qkv, BSr, D3, DD);
        flash_kernel<<<dim3(SS / 64, BH), 128>>>(qkv, abuf);
        h_gemm<2, 64, false, float>
            <<<dim3(BSr / 64, DD / 128), 256, SMEMH(64)>>>(
            abuf, wh + OFF_PROJ + (size_t)l * DD * DD, proj_b + (size_t)l * DD, h,
            h, BSr, DD, DD);
        layernorm_kernel<<<BSr / 8, 256>>>(h, ln2_g + l * DD, ln2_b + l * DD, xln);
        h_gemm<1, 128, false, __half>
            <<<dim3(BSr / 128, D4 / 128), 256, SMEMH(128)>>>(
            xln, wh + OFF_FC + (size_t)l * DD * D4, fc_b + (size_t)l * D4, nullptr,
            fcb, BSr, D4, DD);
        h_gemm<2, 64, false, float>
            <<<dim3(BSr / 64, DD / 128), 256, SMEMH(64)>>>(
            fcb, wh + OFF_FC2 + (size_t)l * D4 * DD, fc2_b + (size_t)l * DD, h,
            h, BSr, DD, D4);
    }

    layernorm_kernel<<<BSr / 8, 256>>>(h, lnf_g, lnf_b, xln);
    h_gemm<3, 128, true, float>
        <<<dim3(BSr / 128, (VV + 127) / 128), 256, SMEMH(128)>>>(
        xln, wh + OFF_WTE, nullptr, nullptr, out, BSr, VV, DD);
}